// round 11
// baseline (speedup 1.0000x reference)
#include <cuda_runtime.h>
#include <cuda_bf16.h>
#include <cuda_fp16.h>
#include <cstdint>

// LightGCN via pull-based CSR gather, fp16 intermediates, degree-sorted
// node scheduling (counting sort, 64 bins) to kill warp divergence.
// deg = clamp(segsum(w by dst), 1); norm = deg^-1/2
// repeat 2x: h = segsum((h*norm)[src] * w, by dst) * norm
// out = mean(h0, h1, h2) -- assembled in the final gather.

#define NN     100000
#define EE     1600000
#define SCAN_B 256
#define NB_MAX 512                       // >= ceil(NN/SCAN_B) = 391
#define NBINS  64

__device__ float   g_deg[NN];            // zero at load; re-zeroed each launch
__device__ int     g_cnt[NN];            // "
__device__ float   g_norm[NN];
__device__ int     g_rowptr[NN + 1];
__device__ int     g_rank[EE];           // edge slot within its dst bucket
__device__ int     g_bsum[NB_MAX];
__device__ int     g_dbin[NBINS];        // degree histogram (capped)
__device__ int     g_dbin2[NBINS];       // placement cursors
__device__ int     g_order[NN];          // nodes sorted by degree bin
__device__ float2  g_edge[EE];           // .x = bits(src), .y = w
__device__ uint4   g_ha[(size_t)NN * 8]; // layer-1 input (h0*norm), fp16
__device__ uint4   g_hb[(size_t)NN * 8]; // layer-2 input (h1*norm), fp16

// ---------------- CSR build ----------------

__global__ void k_hist(const float* __restrict__ w,
                       const int* __restrict__ dst, int e) {
    int i = blockIdx.x * blockDim.x + threadIdx.x;
    if (i >= e) return;
    int d = dst[i];
    asm volatile("red.global.add.f32 [%0], %1;"
                 :: "l"(&g_deg[d]), "f"(w[i]) : "memory");
    g_rank[i] = atomicAdd(&g_cnt[d], 1);
}

// per-block (256-node) exclusive scan of cnt -> rowptr(local); totals -> bsum.
// Block 0 also zeroes the degree-bin arrays for this replay.
__global__ void k_scanA(int n) {
    __shared__ int sh[8];
    if (blockIdx.x == 0 && threadIdx.x < NBINS) {
        g_dbin[threadIdx.x] = 0;
        g_dbin2[threadIdx.x] = 0;
    }
    int i = blockIdx.x * SCAN_B + threadIdx.x;
    int lane = threadIdx.x & 31, wid = threadIdx.x >> 5;
    int v = (i < n) ? g_cnt[i] : 0;
    int x = v;
    #pragma unroll
    for (int o = 1; o < 32; o <<= 1) {
        int y = __shfl_up_sync(0xffffffffu, x, o);
        if (lane >= o) x += y;
    }
    if (lane == 31) sh[wid] = x;
    __syncthreads();
    if (threadIdx.x == 0) {
        int acc = 0;
        #pragma unroll
        for (int k = 0; k < 8; k++) { int t = sh[k]; sh[k] = acc; acc += t; }
        g_bsum[blockIdx.x] = acc;
    }
    __syncthreads();
    int excl = x - v + sh[wid];
    if (i < n) g_rowptr[i] = excl;
}

// finalize rowptr (+block offset), compute norm, histogram degree bins
__global__ void k_scanC(int n, int e) {
    __shared__ int s_off;
    int t = threadIdx.x;
    int lane = t & 31;
    if (t < 32) {
        int acc = 0;
        for (int k = lane; k < blockIdx.x; k += 32) acc += g_bsum[k];
        #pragma unroll
        for (int o = 16; o > 0; o >>= 1)
            acc += __shfl_down_sync(0xffffffffu, acc, o);
        if (lane == 0) s_off = acc;
    }
    __syncthreads();
    int i = blockIdx.x * SCAN_B + t;
    if (i < n) {
        g_rowptr[i] += s_off;
        g_norm[i] = rsqrtf(fmaxf(g_deg[i], 1.0f));
        if (i == 0) g_rowptr[n] = e;
        // degree-bin histogram (warp-aggregated)
        int bin = min(g_cnt[i], NBINS - 1);
        unsigned act = __activemask();
        unsigned mk = __match_any_sync(act, bin);
        int leader = __ffs(mk) - 1;
        if (lane == leader) atomicAdd(&g_dbin[bin], __popc(mk));
    }
}

// fused: fill CSR [0,fb) + prep g_ha [fb,fb+pb) + degree-sort nodes [fb+pb,...)
__global__ void k_prepfill(const float4* __restrict__ h,
                           const int* __restrict__ src,
                           const int* __restrict__ dst,
                           const float* __restrict__ w,
                           int e, int n16, int n, int fb, int pb) {
    if (blockIdx.x < fb) {
        int i = blockIdx.x * blockDim.x + threadIdx.x;
        if (i >= e) return;
        int pos = g_rowptr[dst[i]] + g_rank[i];
        g_edge[pos] = make_float2(__int_as_float(src[i]), w[i]);
    } else if (blockIdx.x < fb + pb) {
        int idx4 = (blockIdx.x - fb) * blockDim.x + threadIdx.x;
        if (idx4 >= n16) return;
        int node = idx4 >> 4;
        if (idx4 < NN) { g_deg[idx4] = 0.0f; g_cnt[idx4] = 0; }
        float nm = __ldg(&g_norm[node]);
        float4 v = h[idx4];
        __half2 a = __floats2half2_rn(v.x * nm, v.y * nm);
        __half2 b = __floats2half2_rn(v.z * nm, v.w * nm);
        uint2 pk = make_uint2(*reinterpret_cast<uint32_t*>(&a),
                              *reinterpret_cast<uint32_t*>(&b));
        reinterpret_cast<uint2*>(g_ha)[idx4] = pk;
    } else {
        // counting-sort placement: g_order[pref[bin] + cursor] = node
        __shared__ int s_pref[NBINS];
        if (threadIdx.x == 0) {
            int acc = 0;
            #pragma unroll
            for (int k = 0; k < NBINS; k++) { int t = g_dbin[k]; s_pref[k] = acc; acc += t; }
        }
        __syncthreads();
        int node = (blockIdx.x - fb - pb) * blockDim.x + threadIdx.x;
        if (node < n) {
            int deg = g_rowptr[node + 1] - g_rowptr[node];
            int bin = min(deg, NBINS - 1);
            int lane = threadIdx.x & 31;
            unsigned act = __activemask();
            unsigned mk = __match_any_sync(act, bin);
            int leader = __ffs(mk) - 1;
            int rank = __popc(mk & ((1u << lane) - 1));
            int base = 0;
            if (lane == leader) base = atomicAdd(&g_dbin2[bin], __popc(mk));
            base = __shfl_sync(mk, base, leader);
            g_order[s_pref[bin] + base + rank] = node;
        }
    }
}

// ---------------- gather layers ----------------

// 8 lanes per node (degree-sorted order); lane sub owns one uint4 (8 fp16 dims).
template <int LAYER>
__device__ __forceinline__ void acc8(float* acc, uint4 r, float wt) {
    const __half2* hp = reinterpret_cast<const __half2*>(&r);
    #pragma unroll
    for (int k = 0; k < 4; k++) {
        float2 f = __half22float2(hp[k]);
        acc[2 * k]     += f.x * wt;
        acc[2 * k + 1] += f.y * wt;
    }
}

template <int LAYER>
__global__ void k_gather(const float4* __restrict__ h4,
                         float4* __restrict__ out, int n) {
    const uint4* rows = (LAYER == 0) ? g_ha : g_hb;
    int gidx = (blockIdx.x * blockDim.x + threadIdx.x) >> 3;
    int sub = threadIdx.x & 7;
    if (gidx >= n) return;
    int gid = g_order[gidx];                    // degree-sorted node id
    int beg = g_rowptr[gid];
    int end = g_rowptr[gid + 1];

    float acc[8] = {0.f, 0.f, 0.f, 0.f, 0.f, 0.f, 0.f, 0.f};
    int j = beg;
    for (; j + 4 <= end; j += 4) {
        float2 e0 = g_edge[j],     e1 = g_edge[j + 1];
        float2 e2 = g_edge[j + 2], e3 = g_edge[j + 3];
        uint4 r0 = rows[(size_t)__float_as_int(e0.x) * 8 + sub];
        uint4 r1 = rows[(size_t)__float_as_int(e1.x) * 8 + sub];
        uint4 r2 = rows[(size_t)__float_as_int(e2.x) * 8 + sub];
        uint4 r3 = rows[(size_t)__float_as_int(e3.x) * 8 + sub];
        acc8<LAYER>(acc, r0, e0.y);
        acc8<LAYER>(acc, r1, e1.y);
        acc8<LAYER>(acc, r2, e2.y);
        acc8<LAYER>(acc, r3, e3.y);
    }
    for (; j < end; ++j) {
        float2 e = g_edge[j];
        uint4 r = rows[(size_t)__float_as_int(e.x) * 8 + sub];
        acc8<LAYER>(acc, r, e.y);
    }

    float nm = g_norm[gid];
    if (LAYER == 0) {
        float s = nm * nm;                       // h1*norm = sum*norm^2
        __half2 o0 = __floats2half2_rn(acc[0] * s, acc[1] * s);
        __half2 o1 = __floats2half2_rn(acc[2] * s, acc[3] * s);
        __half2 o2 = __floats2half2_rn(acc[4] * s, acc[5] * s);
        __half2 o3 = __floats2half2_rn(acc[6] * s, acc[7] * s);
        uint4 st = make_uint4(*reinterpret_cast<uint32_t*>(&o0),
                              *reinterpret_cast<uint32_t*>(&o1),
                              *reinterpret_cast<uint32_t*>(&o2),
                              *reinterpret_cast<uint32_t*>(&o3));
        g_hb[(size_t)gid * 8 + sub] = st;
    } else {
        float rin = __frcp_rn(nm);               // 1/norm, norm in (0,1]
        uint4 hb = g_hb[(size_t)gid * 8 + sub];
        const __half2* hp = reinterpret_cast<const __half2*>(&hb);
        float h1[8];
        #pragma unroll
        for (int k = 0; k < 4; k++) {
            float2 f = __half22float2(hp[k]);
            h1[2 * k]     = f.x * rin;
            h1[2 * k + 1] = f.y * rin;
        }
        size_t b4 = (size_t)gid * 16 + sub * 2;
        float4 h0a = h4[b4], h0b = h4[b4 + 1];
        const float third = 1.0f / 3.0f;
        float4 oa, ob;
        oa.x = (h0a.x + h1[0] + acc[0] * nm) * third;
        oa.y = (h0a.y + h1[1] + acc[1] * nm) * third;
        oa.z = (h0a.z + h1[2] + acc[2] * nm) * third;
        oa.w = (h0a.w + h1[3] + acc[3] * nm) * third;
        ob.x = (h0b.x + h1[4] + acc[4] * nm) * third;
        ob.y = (h0b.y + h1[5] + acc[5] * nm) * third;
        ob.z = (h0b.z + h1[6] + acc[6] * nm) * third;
        ob.w = (h0b.w + h1[7] + acc[7] * nm) * third;
        out[b4] = oa;
        out[b4 + 1] = ob;
    }
}

extern "C" void kernel_launch(void* const* d_in, const int* in_sizes, int n_in,
                              void* d_out, int out_size) {
    const float* h   = (const float*)d_in[0];
    const float* w   = (const float*)d_in[1];
    const int*   src = (const int*)d_in[2];
    const int*   dst = (const int*)d_in[3];
    float* out = (float*)d_out;

    const int N   = in_sizes[0] / 64;   // 100000
    const int E   = in_sizes[1];        // 1600000
    const int B   = 256;
    const int nb  = (N + SCAN_B - 1) / SCAN_B;   // 391
    const int N16 = N * 16;
    const int fb  = (E + B - 1) / B;             // fill blocks
    const int pb  = (N16 + B - 1) / B;           // prep blocks
    const int sb  = (N + B - 1) / B;             // sort blocks

    k_hist    <<<(E + B - 1) / B, B>>>(w, dst, E);
    k_scanA   <<<nb, SCAN_B>>>(N);
    k_scanC   <<<nb, SCAN_B>>>(N, E);
    k_prepfill<<<fb + pb + sb, B>>>((const float4*)h, src, dst, w,
                                    E, N16, N, fb, pb);

    const int ggrid = (N * 8 + B - 1) / B;       // 8 lanes per node
    k_gather<0><<<ggrid, B>>>((const float4*)h, (float4*)out, N);
    k_gather<1><<<ggrid, B>>>((const float4*)h, (float4*)out, N);
}

// round 12
// speedup vs baseline: 1.0977x; 1.0977x over previous
#include <cuda_runtime.h>
#include <cuda_bf16.h>
#include <cuda_fp16.h>
#include <cstdint>

// LightGCN via pull-based CSR gather, fp16 intermediate embeddings.
// deg = clamp(segsum(w by dst), 1); norm = deg^-1/2
// repeat 2x: h = segsum((h*norm)[src] * w, by dst) * norm
// out = mean(h0, h1, h2) -- assembled in the final gather.
//
// Gather: 8 lanes per node, unroll-8 -> 32 outstanding 16B row loads per warp.

#define NN     100000
#define EE     1600000
#define SCAN_B 256
#define NB_MAX 512                       // >= ceil(NN/SCAN_B) = 391

__device__ float    g_deg[NN];           // zero at load; re-zeroed each launch
__device__ int      g_cnt[NN];           // "
__device__ float    g_norm[NN];
__device__ int      g_rowptr[NN + 1];
__device__ unsigned short g_rank[EE];    // edge slot within its dst bucket
__device__ int      g_bsum[NB_MAX];
__device__ float2   g_edge[EE];          // .x = bits(src), .y = w
__device__ uint4    g_ha[(size_t)NN * 8];// layer-1 input (h0*norm), fp16
__device__ uint4    g_hb[(size_t)NN * 8];// layer-2 input (h1*norm), fp16

// ---------------- CSR build ----------------

__global__ void k_hist(const float* __restrict__ w,
                       const int* __restrict__ dst, int e) {
    int i = blockIdx.x * blockDim.x + threadIdx.x;
    if (i >= e) return;
    int d = dst[i];
    asm volatile("red.global.add.f32 [%0], %1;"
                 :: "l"(&g_deg[d]), "f"(w[i]) : "memory");
    g_rank[i] = (unsigned short)atomicAdd(&g_cnt[d], 1);
}

// per-block (256-node) exclusive scan of cnt -> rowptr(local); totals -> bsum
__global__ void k_scanA(int n) {
    __shared__ int sh[8];
    int i = blockIdx.x * SCAN_B + threadIdx.x;
    int lane = threadIdx.x & 31, wid = threadIdx.x >> 5;
    int v = (i < n) ? g_cnt[i] : 0;
    int x = v;
    #pragma unroll
    for (int o = 1; o < 32; o <<= 1) {
        int y = __shfl_up_sync(0xffffffffu, x, o);
        if (lane >= o) x += y;
    }
    if (lane == 31) sh[wid] = x;
    __syncthreads();
    if (threadIdx.x == 0) {
        int acc = 0;
        #pragma unroll
        for (int k = 0; k < 8; k++) { int t = sh[k]; sh[k] = acc; acc += t; }
        g_bsum[blockIdx.x] = acc;
    }
    __syncthreads();
    int excl = x - v + sh[wid];
    if (i < n) g_rowptr[i] = excl;
}

// finalize rowptr (+block offset) and compute norm
__global__ void k_scanC(int n, int e) {
    __shared__ int s_off;
    int t = threadIdx.x;
    int lane = t & 31;
    if (t < 32) {
        int acc = 0;
        for (int k = lane; k < blockIdx.x; k += 32) acc += g_bsum[k];
        #pragma unroll
        for (int o = 16; o > 0; o >>= 1)
            acc += __shfl_down_sync(0xffffffffu, acc, o);
        if (lane == 0) s_off = acc;
    }
    __syncthreads();
    int i = blockIdx.x * SCAN_B + t;
    if (i < n) {
        g_rowptr[i] += s_off;
        g_norm[i] = rsqrtf(fmaxf(g_deg[i], 1.0f));
        if (i == 0) g_rowptr[n] = e;
    }
}

// fused: fill CSR (blocks [0, fb)) + prep g_ha (blocks [fb, ...)).
// Re-zeroes g_deg/g_cnt for the next graph replay.
__global__ void k_prepfill(const float4* __restrict__ h,
                           const int* __restrict__ src,
                           const int* __restrict__ dst,
                           const float* __restrict__ w,
                           int e, int n16, int fb) {
    if (blockIdx.x < fb) {
        int i = blockIdx.x * blockDim.x + threadIdx.x;
        if (i >= e) return;
        int pos = g_rowptr[dst[i]] + (int)g_rank[i];
        g_edge[pos] = make_float2(__int_as_float(src[i]), w[i]);
    } else {
        int idx4 = (blockIdx.x - fb) * blockDim.x + threadIdx.x;
        if (idx4 >= n16) return;
        int node = idx4 >> 4;
        if (idx4 < NN) { g_deg[idx4] = 0.0f; g_cnt[idx4] = 0; }
        float nm = __ldg(&g_norm[node]);
        float4 v = h[idx4];
        __half2 a = __floats2half2_rn(v.x * nm, v.y * nm);
        __half2 b = __floats2half2_rn(v.z * nm, v.w * nm);
        uint2 pk = make_uint2(*reinterpret_cast<uint32_t*>(&a),
                              *reinterpret_cast<uint32_t*>(&b));
        reinterpret_cast<uint2*>(g_ha)[idx4] = pk;
    }
}

// ---------------- gather layers ----------------

// 8 lanes per node; lane sub owns dims [sub*8, sub*8+8) = one uint4 of fp16.
// LAYER=0: read g_ha; g_hb = fp16(sum * norm^2).
// LAYER=1: read g_hb; out = (h0 + hb_own/norm + sum*norm) / 3.
__device__ __forceinline__ void acc8(float* acc, uint4 r, float wt) {
    const __half2* hp = reinterpret_cast<const __half2*>(&r);
    #pragma unroll
    for (int k = 0; k < 4; k++) {
        float2 f = __half22float2(hp[k]);
        acc[2 * k]     += f.x * wt;
        acc[2 * k + 1] += f.y * wt;
    }
}

template <int LAYER>
__global__ void k_gather(const float4* __restrict__ h4,
                         float4* __restrict__ out, int n) {
    const uint4* rows = (LAYER == 0) ? g_ha : g_hb;
    int gid = (blockIdx.x * blockDim.x + threadIdx.x) >> 3;   // node
    int sub = threadIdx.x & 7;
    if (gid >= n) return;
    int beg = g_rowptr[gid];
    int end = g_rowptr[gid + 1];

    float acc[8] = {0.f, 0.f, 0.f, 0.f, 0.f, 0.f, 0.f, 0.f};
    int j = beg;
    for (; j + 8 <= end; j += 8) {
        float2 e0 = g_edge[j],     e1 = g_edge[j + 1];
        float2 e2 = g_edge[j + 2], e3 = g_edge[j + 3];
        float2 e4 = g_edge[j + 4], e5 = g_edge[j + 5];
        float2 e6 = g_edge[j + 6], e7 = g_edge[j + 7];
        uint4 r0 = rows[(size_t)__float_as_int(e0.x) * 8 + sub];
        uint4 r1 = rows[(size_t)__float_as_int(e1.x) * 8 + sub];
        uint4 r2 = rows[(size_t)__float_as_int(e2.x) * 8 + sub];
        uint4 r3 = rows[(size_t)__float_as_int(e3.x) * 8 + sub];
        uint4 r4 = rows[(size_t)__float_as_int(e4.x) * 8 + sub];
        uint4 r5 = rows[(size_t)__float_as_int(e5.x) * 8 + sub];
        uint4 r6 = rows[(size_t)__float_as_int(e6.x) * 8 + sub];
        uint4 r7 = rows[(size_t)__float_as_int(e7.x) * 8 + sub];
        acc8(acc, r0, e0.y); acc8(acc, r1, e1.y);
        acc8(acc, r2, e2.y); acc8(acc, r3, e3.y);
        acc8(acc, r4, e4.y); acc8(acc, r5, e5.y);
        acc8(acc, r6, e6.y); acc8(acc, r7, e7.y);
    }
    if (j + 4 <= end) {
        float2 e0 = g_edge[j],     e1 = g_edge[j + 1];
        float2 e2 = g_edge[j + 2], e3 = g_edge[j + 3];
        uint4 r0 = rows[(size_t)__float_as_int(e0.x) * 8 + sub];
        uint4 r1 = rows[(size_t)__float_as_int(e1.x) * 8 + sub];
        uint4 r2 = rows[(size_t)__float_as_int(e2.x) * 8 + sub];
        uint4 r3 = rows[(size_t)__float_as_int(e3.x) * 8 + sub];
        acc8(acc, r0, e0.y); acc8(acc, r1, e1.y);
        acc8(acc, r2, e2.y); acc8(acc, r3, e3.y);
        j += 4;
    }
    for (; j < end; ++j) {
        float2 e = g_edge[j];
        uint4 r = rows[(size_t)__float_as_int(e.x) * 8 + sub];
        acc8(acc, r, e.y);
    }

    float nm = g_norm[gid];
    if (LAYER == 0) {
        float s = nm * nm;                       // h1*norm = sum*norm^2
        __half2 o0 = __floats2half2_rn(acc[0] * s, acc[1] * s);
        __half2 o1 = __floats2half2_rn(acc[2] * s, acc[3] * s);
        __half2 o2 = __floats2half2_rn(acc[4] * s, acc[5] * s);
        __half2 o3 = __floats2half2_rn(acc[6] * s, acc[7] * s);
        uint4 st = make_uint4(*reinterpret_cast<uint32_t*>(&o0),
                              *reinterpret_cast<uint32_t*>(&o1),
                              *reinterpret_cast<uint32_t*>(&o2),
                              *reinterpret_cast<uint32_t*>(&o3));
        g_hb[(size_t)gid * 8 + sub] = st;
    } else {
        float rin = __frcp_rn(nm);               // 1/norm, norm in (0,1]
        uint4 hb = g_hb[(size_t)gid * 8 + sub];
        const __half2* hp = reinterpret_cast<const __half2*>(&hb);
        float h1[8];
        #pragma unroll
        for (int k = 0; k < 4; k++) {
            float2 f = __half22float2(hp[k]);
            h1[2 * k]     = f.x * rin;
            h1[2 * k + 1] = f.y * rin;
        }
        size_t b4 = (size_t)gid * 16 + sub * 2;  // float4 index into h0/out
        float4 h0a = h4[b4], h0b = h4[b4 + 1];
        const float third = 1.0f / 3.0f;
        float4 oa, ob;
        oa.x = (h0a.x + h1[0] + acc[0] * nm) * third;
        oa.y = (h0a.y + h1[1] + acc[1] * nm) * third;
        oa.z = (h0a.z + h1[2] + acc[2] * nm) * third;
        oa.w = (h0a.w + h1[3] + acc[3] * nm) * third;
        ob.x = (h0b.x + h1[4] + acc[4] * nm) * third;
        ob.y = (h0b.y + h1[5] + acc[5] * nm) * third;
        ob.z = (h0b.z + h1[6] + acc[6] * nm) * third;
        ob.w = (h0b.w + h1[7] + acc[7] * nm) * third;
        out[b4] = oa;
        out[b4 + 1] = ob;
    }
}

extern "C" void kernel_launch(void* const* d_in, const int* in_sizes, int n_in,
                              void* d_out, int out_size) {
    const float* h   = (const float*)d_in[0];
    const float* w   = (const float*)d_in[1];
    const int*   src = (const int*)d_in[2];
    const int*   dst = (const int*)d_in[3];
    float* out = (float*)d_out;

    const int N   = in_sizes[0] / 64;   // 100000
    const int E   = in_sizes[1];        // 1600000
    const int B   = 256;
    const int nb  = (N + SCAN_B - 1) / SCAN_B;   // 391
    const int N16 = N * 16;
    const int fb  = (E + B - 1) / B;             // fill blocks
    const int pb  = (N16 + B - 1) / B;           // prep blocks

    k_hist    <<<(E + B - 1) / B, B>>>(w, dst, E);
    k_scanA   <<<nb, SCAN_B>>>(N);
    k_scanC   <<<nb, SCAN_B>>>(N, E);
    k_prepfill<<<fb + pb, B>>>((const float4*)h, src, dst, w, E, N16, fb);

    const int ggrid = (N * 8 + B - 1) / B;       // 8 lanes per node
    k_gather<0><<<ggrid, B>>>((const float4*)h, (float4*)out, N);
    k_gather<1><<<ggrid, B>>>((const float4*)h, (float4*)out, N);
}